// round 1
// baseline (speedup 1.0000x reference)
#include <cuda_runtime.h>
#include <cstdint>
#include <cstddef>

#define TT 512
#define CC 128
#define LL 80
#define SS 161
#define BLANKC 127
#define FEPS 1e-7f
#define PIPE 8
#define FULLM 0xffffffffu

__device__ __forceinline__ void cp_async16(void* smem, const void* gmem) {
    unsigned s = (unsigned)__cvta_generic_to_shared(smem);
    asm volatile("cp.async.cg.shared.global [%0], [%1], 16;\n" :: "r"(s), "l"(gmem));
}
__device__ __forceinline__ void cp_commit() {
    asm volatile("cp.async.commit_group;\n" ::: "memory");
}
__device__ __forceinline__ void cp_waitg() {
    asm volatile("cp.async.wait_group %0;\n" :: "n"(PIPE - 2) : "memory");
}

// One warp handles one batch element. Lane holds states s = 5*lane + j (j=0..4),
// lane 31 additionally holds s=160 (j=5). Forward recursion kept in linear
// probability space with lagged rescaling; all rescale factors and per-row
// softmax norms are accounted exactly in double-precision log accumulators.
__global__ void __launch_bounds__(128, 1) ctc_fwd_kernel(
    const int* __restrict__ lab32,
    const float* __restrict__ ypred,
    float* __restrict__ out)
{
    __shared__ __align__(16) float ring[4][PIPE][CC];
    const int warp = threadIdx.x >> 5;
    const int lane = threadIdx.x & 31;
    const int b = blockIdx.x * 4 + warp;
    float (*rw)[CC] = ring[warp];
    const float* __restrict__ yb = ypred + (size_t)b * (TT * CC);

    // ---- detect label element width (int64 little-endian vs int32) ----
    int probe = lab32[1] | lab32[3] | lab32[5] | lab32[7]
              | lab32[9] | lab32[11] | lab32[13] | lab32[15];
    const int stride = (probe == 0) ? 2 : 1;
    const int* lb = lab32 + (size_t)b * LL * stride;

    // ---- per-state extended symbol + skip-transition mask ----
    int ext[6];
    float allow[6];
#pragma unroll
    for (int j = 0; j < 6; j++) {
        int s = 5 * lane + j;
        int e = BLANKC;
        float al = 0.f;
        if (s < SS && (s & 1)) {
            int li = s >> 1;
            e = lb[li * stride];
            if (s >= 3) {
                int pm = lb[(li - 1) * stride];
                al = (e != pm) ? 1.f : 0.f;
            }
        }
        ext[j] = e;
        allow[j] = al;
    }

    // ---- prime cp.async ring with rows 0..PIPE-2 ----
#pragma unroll
    for (int r = 0; r < PIPE - 1; r++) {
        cp_async16(&rw[r][lane * 4], yb + (size_t)r * CC + lane * 4);
        cp_commit();
    }

    float a0 = 0.f, a1 = 0.f, a2 = 0.f, a3 = 0.f, a4 = 0.f, a5 = 0.f;
    // software-pipelined norm reduction registers (row t-1-k at stage k)
    float np0 = 0.f, np1 = 0.f, np2 = 0.f, np3 = 0.f, np4 = 0.f;
    double accN = 0.0, accS = 0.0;     // sum log(norm_t), sum log(applied rescale)
    float c = 1.f, ec = FEPS;          // active rescale multiplier: q*c = y*c + ec
    float rs = 0.f, pend = 0.f, cN = 1.f, ecN = FEPS;
    int t = 0;

#define CTC_STEP(FIRST, U) do {                                                     \
    cp_waitg();                                                                     \
    __syncwarp();                                                                   \
    { int r_ = t + (PIPE - 1);                                                      \
      if (r_ < TT) cp_async16(&rw[r_ & (PIPE - 1)][lane * 4],                       \
                              yb + (size_t)r_ * CC + lane * 4);                     \
      cp_commit(); }                                                                \
    const float* yrow = rw[t & (PIPE - 1)];                                         \
    float4 v4 = *(const float4*)(yrow + lane * 4);                                  \
    float loc = (v4.x + v4.y) + (v4.z + v4.w);                                      \
    /* norm pipeline: finish row t-5 (valid once t>=5) */                           \
    if (!(FIRST) || (U) >= 5) {                                                     \
        float fin = np4 + __shfl_xor_sync(FULLM, np4, 1);                           \
        accN += (double)__logf(fin + (float)CC * FEPS);                             \
    }                                                                               \
    np4 = np3 + __shfl_xor_sync(FULLM, np3, 2);                                     \
    np3 = np2 + __shfl_xor_sync(FULLM, np2, 4);                                     \
    np2 = np1 + __shfl_xor_sync(FULLM, np1, 8);                                     \
    np1 = np0 + __shfl_xor_sync(FULLM, np0, 16);                                    \
    np0 = loc;                                                                      \
    if ((FIRST) && (U) == 0) {                                                      \
        a0 = (lane == 0) ? yrow[ext[0]] + FEPS : 0.f;                               \
        a1 = (lane == 0) ? yrow[ext[1]] + FEPS : 0.f;                               \
        a2 = 0.f; a3 = 0.f; a4 = 0.f; a5 = 0.f;                                     \
    } else {                                                                        \
        float p4s = __shfl_up_sync(FULLM, a4, 1);                                   \
        float p3s = __shfl_up_sync(FULLM, a3, 1);                                   \
        if (lane == 0) { p4s = 0.f; p3s = 0.f; }                                    \
        float q0 = __fmaf_rn(yrow[ext[0]], c, ec);                                  \
        float q1 = __fmaf_rn(yrow[ext[1]], c, ec);                                  \
        float q2 = __fmaf_rn(yrow[ext[2]], c, ec);                                  \
        float q3 = __fmaf_rn(yrow[ext[3]], c, ec);                                  \
        float q4 = __fmaf_rn(yrow[ext[4]], c, ec);                                  \
        float q5 = __fmaf_rn(yrow[ext[5]], c, ec);                                  \
        float t0 = __fmaf_rn(allow[0], p3s, a0 + p4s);                              \
        float t1 = __fmaf_rn(allow[1], p4s, a1 + a0);                               \
        float t2 = __fmaf_rn(allow[2], a0,  a2 + a1);                               \
        float t3 = __fmaf_rn(allow[3], a1,  a3 + a2);                               \
        float t4 = __fmaf_rn(allow[4], a2,  a4 + a3);                               \
        float t5 = __fmaf_rn(allow[5], a3,  a5 + a4);                               \
        a0 = q0 * t0; a1 = q1 * t1; a2 = q2 * t2; a3 = q3 * t3; a4 = q4 * t4;       \
        a5 = (lane == 31) ? q5 * t5 : 0.f;                                          \
        if ((U) == 0 && !(FIRST)) { accS += (double)pend; }                         \
        c = 1.f; ec = FEPS;                                                         \
    }                                                                               \
    /* lagged rescale: one butterfly stage per step, applied next group at U==0 */  \
    if ((U) == 0)      { rs = ((a0 + a1) + (a2 + a3)) + (a4 + a5); }                \
    else if ((U) == 1) { rs += __shfl_xor_sync(FULLM, rs, 16); }                    \
    else if ((U) == 2) { rs += __shfl_xor_sync(FULLM, rs, 8); }                     \
    else if ((U) == 3) { rs += __shfl_xor_sync(FULLM, rs, 4); }                     \
    else if ((U) == 4) { rs += __shfl_xor_sync(FULLM, rs, 2); }                     \
    else if ((U) == 5) { rs += __shfl_xor_sync(FULLM, rs, 1); }                     \
    else if ((U) == 6) { pend = __logf(rs); cN = 1.f / rs; ecN = FEPS * cN; }       \
    else               { c = cN; ec = ecN; }                                        \
    t++;                                                                            \
} while (0)

    // first group: t=0 init + t=1..7 updates
    CTC_STEP(1, 0); CTC_STEP(1, 1); CTC_STEP(1, 2); CTC_STEP(1, 3);
    CTC_STEP(1, 4); CTC_STEP(1, 5); CTC_STEP(1, 6); CTC_STEP(1, 7);

#pragma unroll 1
    for (int g = 1; g < TT / 8; g++) {
        CTC_STEP(0, 0); CTC_STEP(0, 1); CTC_STEP(0, 2); CTC_STEP(0, 3);
        CTC_STEP(0, 4); CTC_STEP(0, 5); CTC_STEP(0, 6); CTC_STEP(0, 7);
    }
#undef CTC_STEP

    // drain norm pipeline (rows TT-5 .. TT-1)
#pragma unroll
    for (int d = 0; d < 5; d++) {
        float fin = np4 + __shfl_xor_sync(FULLM, np4, 1);
        accN += (double)__logf(fin + (float)CC * FEPS);
        np4 = np3 + __shfl_xor_sync(FULLM, np3, 2);
        np3 = np2 + __shfl_xor_sync(FULLM, np2, 4);
        np2 = np1 + __shfl_xor_sync(FULLM, np1, 8);
        np1 = np0 + __shfl_xor_sync(FULLM, np0, 16);
        np0 = 0.f;
    }

    // loss = -( log(A[S-1]+A[S-2]) + sum(applied rescale logs) - sum(log norms) )
    float tail = a4 + a5;   // lane 31: states 159 + 160
    if (lane == 31) {
        out[b] = -(__logf(tail) + (float)(accS - accN));
    }
}

extern "C" void kernel_launch(void* const* d_in, const int* in_sizes, int n_in,
                              void* d_out, int out_size) {
    (void)in_sizes; (void)n_in; (void)out_size;
    const int* labels = (const int*)d_in[0];
    const float* ypred = (const float*)d_in[1];
    float* out = (float*)d_out;
    ctc_fwd_kernel<<<128, 128>>>(labels, ypred, out);
}

// round 2
// speedup vs baseline: 1.1410x; 1.1410x over previous
#include <cuda_runtime.h>
#include <cstdint>
#include <cstddef>

#define TT 512
#define CC 128
#define LL 80
#define BLANKC 127
#define FEPS 1e-7f
#define FULLM 0xffffffffu
#define DPF 8

// One warp per batch element. States split by parity:
//  e_i = alpha[2i]   (blank states, i=0..80): lane l holds e_l, e_{32+l}, e_{64+l}
//  o_i = alpha[2i+1] (label states, i=0..79): lane l holds o_l, o_{32+l}, o_{64+l}
// Blank emission prob is ONE scalar per row (y[t][127]) -> 1 uniform LDG;
// label gathers are 3 LDGs, prefetched DPF rows ahead in registers (no smem).
// Linear-domain recursion with 8-step lagged rescaling; softmax log-norms
// computed in a 5-stage software-pipelined butterfly, all float accumulators.
__global__ void __launch_bounds__(128, 1) ctc_kernel(
    const int* __restrict__ lab32,
    const float* __restrict__ ypred,
    float* __restrict__ out)
{
    const int lane = threadIdx.x & 31;
    const int w = threadIdx.x >> 5;
    const int b = blockIdx.x * 4 + w;
    const float* __restrict__ yb = ypred + (size_t)b * (TT * CC);

    // detect label element width (int64 little-endian vs int32)
    int probe = lab32[1] | lab32[3] | lab32[5] | lab32[7]
              | lab32[9] | lab32[11] | lab32[13] | lab32[15];
    const int stride = (probe == 0) ? 2 : 1;
    const int* lb = lab32 + (size_t)b * LL * stride;

    const int i1 = 32 + lane, i2 = 64 + lane;
    const int L0 = lb[lane * stride];
    const int L1 = lb[i1 * stride];
    const bool v2 = (i2 < LL);
    const int L2 = v2 ? lb[i2 * stride] : BLANKC;
    const float al0 = (lane == 0) ? 0.f : ((L0 != lb[(lane - 1) * stride]) ? 1.f : 0.f);
    const float al1 = (L1 != lb[(i1 - 1) * stride]) ? 1.f : 0.f;
    const float al2 = (v2 && (L2 != lb[(i2 - 1) * stride])) ? 1.f : 0.f;

    const float* __restrict__ gB = yb + BLANKC;
    const float* __restrict__ g0 = yb + L0;
    const float* __restrict__ g1 = yb + L1;
    const float* __restrict__ g2 = yb + L2;
    const float* __restrict__ gN = yb + lane * 4;

    // prime DPF-deep gather pipeline (rows 0..DPF-1)
    float qB[DPF], q0[DPF], q1[DPF], q2[DPF];
#pragma unroll
    for (int r = 0; r < DPF; r++) {
        qB[r] = gB[(size_t)r * CC];
        q0[r] = g0[(size_t)r * CC];
        q1[r] = g1[(size_t)r * CC];
        q2[r] = g2[(size_t)r * CC];
    }
    float locc, locn;
    { float4 v = *(const float4*)(gN);            locc = (v.x + v.y) + (v.z + v.w); }
    { float4 v = *(const float4*)(gN + CC);       locn = (v.x + v.y) + (v.z + v.w); }

    float e0 = 0.f, e1 = 0.f, e2 = 0.f, o0 = 0.f, o1 = 0.f, o2 = 0.f;
    float np0 = 0.f, np1 = 0.f, np2 = 0.f, np3 = 0.f, np4 = 0.f;
    float accN0 = 0.f, accN1 = 0.f, accS = 0.f;
    float rs = 0.f, pend = 0.f, cN = 1.f;
    int t = 0;

#define CTC_STEP(FIRST, U) do {                                                     \
    /* consume q slot U (row t), then refill with row t+DPF */                      \
    float yB = qB[U] + FEPS;                                                        \
    float y0 = q0[U] + FEPS;                                                        \
    float y1 = q1[U] + FEPS;                                                        \
    float y2 = v2 ? (q2[U] + FEPS) : 0.f;                                           \
    { int tn = t + DPF;                                                             \
      if (tn < TT) {                                                               \
          qB[U] = gB[(size_t)tn * CC]; q0[U] = g0[(size_t)tn * CC];                 \
          q1[U] = g1[(size_t)tn * CC]; q2[U] = g2[(size_t)tn * CC]; } }            \
    /* norm pipeline: finish row t-5 */                                             \
    if (!(FIRST) || (U) >= 5) {                                                     \
        float fin = np4 + __shfl_xor_sync(FULLM, np4, 1);                           \
        float lg = __logf(fin + (float)CC * FEPS);                                  \
        if (((U) & 1) == 0) accN0 += lg; else accN1 += lg;                          \
    }                                                                               \
    np4 = np3 + __shfl_xor_sync(FULLM, np3, 2);                                     \
    np3 = np2 + __shfl_xor_sync(FULLM, np2, 4);                                     \
    np2 = np1 + __shfl_xor_sync(FULLM, np1, 8);                                     \
    np1 = np0 + __shfl_xor_sync(FULLM, np0, 16);                                    \
    np0 = locc;                                                                     \
    { int tn2 = t + 2; locc = locn;                                                 \
      if (tn2 < TT) { float4 v = *(const float4*)(gN + (size_t)tn2 * CC);           \
                      locn = (v.x + v.y) + (v.z + v.w); }                           \
      else locn = 0.f; }                                                            \
    if ((FIRST) && (U) == 0) {                                                      \
        e0 = (lane == 0) ? yB : 0.f;                                                \
        o0 = (lane == 0) ? y0 : 0.f;                                                \
    } else {                                                                        \
        float bb0 = __shfl_sync(FULLM, o0, 31);                                     \
        float bb1 = __shfl_sync(FULLM, o1, 31);                                     \
        float m0 = __shfl_up_sync(FULLM, o0, 1);                                    \
        float m1 = __shfl_up_sync(FULLM, o1, 1);                                    \
        float m2 = __shfl_up_sync(FULLM, o2, 1);                                    \
        if (lane == 0) { m0 = 0.f; m1 = bb0; m2 = bb1; }                            \
        float ne0 = yB * (e0 + m0);                                                 \
        float ne1 = yB * (e1 + m1);                                                 \
        float ne2 = yB * (e2 + m2);                                                 \
        float no0 = y0 * __fmaf_rn(al0, m0, o0 + e0);                               \
        float no1 = y1 * __fmaf_rn(al1, m1, o1 + e1);                               \
        float no2 = y2 * __fmaf_rn(al2, m2, o2 + e2);                               \
        e0 = ne0; e1 = ne1; e2 = ne2; o0 = no0; o1 = no1; o2 = no2;                 \
    }                                                                               \
    /* lagged rescale: stage per step, applied at U==7 */                           \
    if ((U) == 0)      { rs = ((e0 + e1) + (e2 + o0)) + (o1 + o2); }                \
    else if ((U) == 1) { rs += __shfl_xor_sync(FULLM, rs, 16); }                    \
    else if ((U) == 2) { rs += __shfl_xor_sync(FULLM, rs, 8); }                     \
    else if ((U) == 3) { rs += __shfl_xor_sync(FULLM, rs, 4); }                     \
    else if ((U) == 4) { rs += __shfl_xor_sync(FULLM, rs, 2); }                     \
    else if ((U) == 5) { rs += __shfl_xor_sync(FULLM, rs, 1); }                     \
    else if ((U) == 6) { pend = __logf(rs); cN = __fdividef(1.f, rs); }             \
    else               { e0 *= cN; e1 *= cN; e2 *= cN;                              \
                         o0 *= cN; o1 *= cN; o2 *= cN; accS += pend; }              \
    t++;                                                                            \
} while (0)

    CTC_STEP(1, 0); CTC_STEP(1, 1); CTC_STEP(1, 2); CTC_STEP(1, 3);
    CTC_STEP(1, 4); CTC_STEP(1, 5); CTC_STEP(1, 6); CTC_STEP(1, 7);

#pragma unroll 1
    for (int g = 1; g < TT / 8; g++) {
        CTC_STEP(0, 0); CTC_STEP(0, 1); CTC_STEP(0, 2); CTC_STEP(0, 3);
        CTC_STEP(0, 4); CTC_STEP(0, 5); CTC_STEP(0, 6); CTC_STEP(0, 7);
    }
#undef CTC_STEP

    // drain norm pipeline (rows TT-5 .. TT-1)
#pragma unroll
    for (int d = 0; d < 5; d++) {
        float fin = np4 + __shfl_xor_sync(FULLM, np4, 1);
        float lg = __logf(fin + (float)CC * FEPS);
        if ((d & 1) == 0) accN0 += lg; else accN1 += lg;
        np4 = np3 + __shfl_xor_sync(FULLM, np3, 2);
        np3 = np2 + __shfl_xor_sync(FULLM, np2, 4);
        np2 = np1 + __shfl_xor_sync(FULLM, np1, 8);
        np1 = np0 + __shfl_xor_sync(FULLM, np0, 16);
        np0 = 0.f;
    }

    // tail: states 160 (e_80, lane 16 reg e2) and 159 (o_79, lane 15 reg o2)
    float accN = accN0 + accN1;
    float e80 = __shfl_sync(FULLM, e2, 16);
    float o79 = __shfl_sync(FULLM, o2, 15);
    if (lane == 0) {
        out[b] = -(__logf(e80 + o79) + accS - accN);
    }
}

extern "C" void kernel_launch(void* const* d_in, const int* in_sizes, int n_in,
                              void* d_out, int out_size) {
    (void)in_sizes; (void)n_in; (void)out_size;
    const int* labels = (const int*)d_in[0];
    const float* ypred = (const float*)d_in[1];
    float* out = (float*)d_out;
    ctc_kernel<<<128, 128>>>(labels, ypred, out);
}